// round 2
// baseline (speedup 1.0000x reference)
#include <cuda_runtime.h>
#include <cuda_fp16.h>
#include <math.h>

#define NN    4096
#define INF_  512
#define HID   8
#define OUTF  256
#define MAXD  128

// ---------------- scratch (static device globals) ---------------------------
__device__ int    g_deg[NN];
__device__ int    g_nbr[NN * MAXD];
__device__ float  g_h[NN * HID];      // x @ W1
__device__ float  g_dst1[NN];         // h @ a1[8:16]
__device__ float  g_ph[NN * HID];     // softmax(dst1)[j] * h[j]
__device__ float  g_h2v[NN];          // h1 @ W2
__device__ float  g_d2[NN];           // h2 * a2[1]
__device__ int    g_rows[2][NN];      // [0]=mask==1 (y1,Wa), [1]=mask==0 (y3,Wc)
__device__ int    g_cnt[2];
__device__ int    g_skip3[NN];        // 1 -> row's y3 never read
__device__ __half g_xh [NN * INF_];   // x in fp16
__device__ __half g_y1h[NN * INF_];   // adj   @ x
__device__ __half g_y2h[NN * INF_];   // adj^2 @ x
__device__ __half g_y3h[NN * INF_];   // adj^3 @ x

// ---------------- 1) build neighbor lists (deterministic order) -------------
__global__ void k_build(const float* __restrict__ adj) {
    int row = blockIdx.x;
    int t   = threadIdx.x;           // 256 threads
    const float4* ar = (const float4*)(adj + (size_t)row * NN);

    float4 v[4];
    int cnt = 0;
#pragma unroll
    for (int i = 0; i < 4; i++) {
        v[i] = ar[t + i * 256];
        cnt += (v[i].x != 0.f) + (v[i].y != 0.f) + (v[i].z != 0.f) + (v[i].w != 0.f);
    }

    __shared__ int sc[256];
    sc[t] = cnt;
    __syncthreads();
    for (int d = 1; d < 256; d <<= 1) {
        int val = (t >= d) ? sc[t - d] : 0;
        __syncthreads();
        if (t >= d) sc[t] += val;
        __syncthreads();
    }
    int pos   = sc[t] - cnt;   // exclusive prefix
    int total = sc[255];

    int* nb = g_nbr + (size_t)row * MAXD;
#pragma unroll
    for (int i = 0; i < 4; i++) {
        int base = (t + i * 256) * 4;
        if (v[i].x != 0.f) { if (pos < MAXD) nb[pos] = base + 0; pos++; }
        if (v[i].y != 0.f) { if (pos < MAXD) nb[pos] = base + 1; pos++; }
        if (v[i].z != 0.f) { if (pos < MAXD) nb[pos] = base + 2; pos++; }
        if (v[i].w != 0.f) { if (pos < MAXD) nb[pos] = base + 3; pos++; }
    }
    if (t == 0) g_deg[row] = total < MAXD ? total : MAXD;
    if (row == 0 && t < 2) g_cnt[t] = 0;   // reset per launch
}

// ---------------- 1b) x -> fp16 copy ---------------------------------------
__global__ void k_cvt(const float* __restrict__ x) {
    int i = blockIdx.x * 256 + threadIdx.x;         // 2048 blocks
    float4 v = ((const float4*)x)[i];
    __half2 lo = __floats2half2_rn(v.x, v.y);
    __half2 hi = __floats2half2_rn(v.z, v.w);
    uint2 packed;
    packed.x = *(unsigned*)&lo;
    packed.y = *(unsigned*)&hi;
    ((uint2*)g_xh)[i] = packed;
}

// ---------------- 2) h = x @ W1, dst1 = h @ a1[HID:] ------------------------
__global__ void k_h(const float* __restrict__ x, const float* __restrict__ W1,
                    const float* __restrict__ a1) {
    int lane = threadIdx.x & 31;
    int row  = blockIdx.x * 8 + (threadIdx.x >> 5);
    const float* xr = x + (size_t)row * INF_;

    float acc[HID];
#pragma unroll
    for (int f = 0; f < HID; f++) acc[f] = 0.f;

    for (int k = lane; k < INF_; k += 32) {
        float xv = xr[k];
        float4 wA = *(const float4*)(W1 + k * HID);
        float4 wB = *(const float4*)(W1 + k * HID + 4);
        acc[0] += xv * wA.x; acc[1] += xv * wA.y; acc[2] += xv * wA.z; acc[3] += xv * wA.w;
        acc[4] += xv * wB.x; acc[5] += xv * wB.y; acc[6] += xv * wB.z; acc[7] += xv * wB.w;
    }
#pragma unroll
    for (int f = 0; f < HID; f++)
        for (int o = 16; o; o >>= 1) acc[f] += __shfl_xor_sync(0xffffffffu, acc[f], o);

    if (lane == 0) {
        float d = 0.f;
#pragma unroll
        for (int f = 0; f < HID; f++) {
            g_h[row * HID + f] = acc[f];
            d += acc[f] * a1[HID + f];
        }
        g_dst1[row] = d;
    }
}

// ---------------- 3) softmax over dst1 -> ph = p * h (one block) ------------
__global__ void k_softmax1() {
    __shared__ float sred[32];
    __shared__ float sbc[2];
    int t = threadIdx.x;  // 1024

    float m = -1e30f;
    for (int i = t; i < NN; i += 1024) m = fmaxf(m, g_dst1[i]);
    for (int o = 16; o; o >>= 1) m = fmaxf(m, __shfl_xor_sync(0xffffffffu, m, o));
    if ((t & 31) == 0) sred[t >> 5] = m;
    __syncthreads();
    if (t < 32) {
        float v = sred[t];
        for (int o = 16; o; o >>= 1) v = fmaxf(v, __shfl_xor_sync(0xffffffffu, v, o));
        if (t == 0) sbc[0] = v;
    }
    __syncthreads();
    float M = sbc[0];

    float s = 0.f;
    for (int i = t; i < NN; i += 1024) s += expf(g_dst1[i] - M);
    for (int o = 16; o; o >>= 1) s += __shfl_xor_sync(0xffffffffu, s, o);
    if ((t & 31) == 0) sred[t >> 5] = s;
    __syncthreads();
    if (t < 32) {
        float v = sred[t];
        for (int o = 16; o; o >>= 1) v += __shfl_xor_sync(0xffffffffu, v, o);
        if (t == 0) sbc[1] = v;
    }
    __syncthreads();
    float inv = 1.f / sbc[1];

    for (int i = t; i < NN; i += 1024) {
        float p = expf(g_dst1[i] - M) * inv;
#pragma unroll
        for (int f = 0; f < HID; f++) g_ph[i * HID + f] = p * g_h[i * HID + f];
    }
}

// ---------------- 4) h1 = elu(adj @ ph); h2 = h1@W2; d2 = h2*a2[1] ----------
__global__ void k_gat1(const float* __restrict__ W2, const float* __restrict__ a2) {
    int lane = threadIdx.x & 31;
    int row  = blockIdx.x * 8 + (threadIdx.x >> 5);
    int deg  = g_deg[row];
    const int* nb = g_nbr + (size_t)row * MAXD;

    float acc[HID];
#pragma unroll
    for (int f = 0; f < HID; f++) acc[f] = 0.f;

    for (int t = lane; t < deg; t += 32) {
        int j = nb[t];
        float4 A = *(const float4*)(g_ph + j * HID);
        float4 B = *(const float4*)(g_ph + j * HID + 4);
        acc[0] += A.x; acc[1] += A.y; acc[2] += A.z; acc[3] += A.w;
        acc[4] += B.x; acc[5] += B.y; acc[6] += B.z; acc[7] += B.w;
    }
#pragma unroll
    for (int f = 0; f < HID; f++)
        for (int o = 16; o; o >>= 1) acc[f] += __shfl_xor_sync(0xffffffffu, acc[f], o);

    if (lane == 0) {
        float h2 = 0.f;
#pragma unroll
        for (int f = 0; f < HID; f++) {
            float v = acc[f];
            v = v > 0.f ? v : (expf(v) - 1.f);   // elu
            h2 += v * W2[f];
        }
        g_h2v[row] = h2;
        g_d2[row]  = h2 * a2[1];
    }
}

// ------ 5) fused: softmax(d2) -> q (smem) -> per-row mask + row lists -------
__global__ void k_sm2mask() {
    __shared__ float sq[NN];           // 16 KB
    __shared__ float sred[32];
    __shared__ float sbc[2];
    int t = threadIdx.x;               // 1024

    float m = -1e30f;
    for (int i = t; i < NN; i += 1024) m = fmaxf(m, g_d2[i]);
    for (int o = 16; o; o >>= 1) m = fmaxf(m, __shfl_xor_sync(0xffffffffu, m, o));
    if ((t & 31) == 0) sred[t >> 5] = m;
    __syncthreads();
    if (t < 32) {
        float v = sred[t];
        for (int o = 16; o; o >>= 1) v = fmaxf(v, __shfl_xor_sync(0xffffffffu, v, o));
        if (t == 0) sbc[0] = v;
    }
    __syncthreads();
    float M = sbc[0];

    float s = 0.f;
    for (int i = t; i < NN; i += 1024) s += expf(g_d2[i] - M);
    for (int o = 16; o; o >>= 1) s += __shfl_xor_sync(0xffffffffu, s, o);
    if ((t & 31) == 0) sred[t >> 5] = s;
    __syncthreads();
    if (t < 32) {
        float v = sred[t];
        for (int o = 16; o; o >>= 1) v += __shfl_xor_sync(0xffffffffu, v, o);
        if (t == 0) sbc[1] = v;
    }
    __syncthreads();
    float inv = 1.f / sbc[1];

    for (int i = t; i < NN; i += 1024)
        sq[i] = expf(g_d2[i] - M) * inv * g_h2v[i];
    __syncthreads();

    // per-row neighbor sum over sq (smem), then elu + threshold
    for (int row = t; row < NN; row += 1024) {
        int deg = g_deg[row];
        const int* nb = g_nbr + (size_t)row * MAXD;
        float s2 = 0.f;
        for (int k = 0; k < deg; k++) s2 += sq[nb[k]];
        float sc = s2 > 0.f ? s2 : (expf(s2) - 1.f);   // elu
        int which = (sc > 0.7f) ? 0 : 1;
        g_skip3[row] = (which == 0);
        int pos = atomicAdd(&g_cnt[which], 1);
        g_rows[which][pos] = row;
    }
}

// ---------------- 6) SpMM fp16: dst[row] = sum_{j in N(row)} src[j] ---------
// mode 0: xh -> y1h ; mode 1: y1h -> y2h ; mode 2: y2h -> y3h (gated by skip3)
__global__ void k_spmm_h(int mode) {
    const __half* __restrict__ src =
        (mode == 0) ? g_xh : ((mode == 1) ? g_y1h : g_y2h);
    __half* dst = (mode == 0) ? g_y1h : ((mode == 1) ? g_y2h : g_y3h);

    int row = blockIdx.x;
    if (mode == 2 && g_skip3[row]) return;

    __shared__ int nbs[MAXD];
    int deg = g_deg[row];
    for (int i = threadIdx.x; i < deg; i += 128) nbs[i] = g_nbr[(size_t)row * MAXD + i];
    __syncthreads();

    int c = threadIdx.x << 2;   // 128 threads * 4 halves = 512 cols
    float4 acc = make_float4(0.f, 0.f, 0.f, 0.f);

    int k = 0;
    for (; k + 8 <= deg; k += 8) {
        uint2 r[8];
#pragma unroll
        for (int u = 0; u < 8; u++)
            r[u] = *(const uint2*)(src + (size_t)nbs[k + u] * INF_ + c);
#pragma unroll
        for (int u = 0; u < 8; u++) {
            float2 f0 = __half22float2(*(__half2*)&r[u].x);
            float2 f1 = __half22float2(*(__half2*)&r[u].y);
            acc.x += f0.x; acc.y += f0.y; acc.z += f1.x; acc.w += f1.y;
        }
    }
    for (; k < deg; k++) {
        uint2 rv = *(const uint2*)(src + (size_t)nbs[k] * INF_ + c);
        float2 f0 = __half22float2(*(__half2*)&rv.x);
        float2 f1 = __half22float2(*(__half2*)&rv.y);
        acc.x += f0.x; acc.y += f0.y; acc.z += f1.x; acc.w += f1.y;
    }

    __half2 lo = __floats2half2_rn(acc.x, acc.y);
    __half2 hi = __floats2half2_rn(acc.z, acc.w);
    uint2 packed;
    packed.x = *(unsigned*)&lo;
    packed.y = *(unsigned*)&hi;
    *(uint2*)(dst + (size_t)row * INF_ + c) = packed;
}

// ---------------- 7) routed GEMM (both halves in one launch, fp16 A) --------
// z==0: rows with mask==1, A=g_y1h, W = W_sgc[   0: 512]
// z==1: rows with mask==0, A=g_y3h, W = W_sgc[1024:1536]
__global__ void k_gemm(const float* __restrict__ Wsgc, const float* __restrict__ bias,
                       float* __restrict__ out) {
    __shared__ float As[16][64];
    __shared__ float Bs[16][64];
    __shared__ int   ridx[64];

    int which = blockIdx.z;
    int cnt   = g_cnt[which];
    int rbase = blockIdx.x * 64;
    if (rbase >= cnt) return;

    const __half* A = which ? g_y3h : g_y1h;
    const float*  B = Wsgc + (which ? (size_t)1024 * OUTF : 0) + blockIdx.y * 64;

    int tid = threadIdx.x;   // 256
    if (tid < 64) {
        int li = rbase + tid;
        ridx[tid] = (li < cnt) ? g_rows[which][li] : -1;
    }
    __syncthreads();

    int am = tid >> 2;            // 0..63 : row in tile (A load)
    int ak = (tid & 3) * 4;       // 0,4,8,12 : k sub-offset (A load)
    int bk = tid >> 4;            // 0..15 : k row (B load)
    int bn = (tid & 15) * 4;      // 0..60 : col (B load)

    int arow = ridx[am];
    const __half* aptr = (arow >= 0) ? (A + (size_t)arow * INF_ + ak) : A;

    float acc[4][4];
#pragma unroll
    for (int i = 0; i < 4; i++)
#pragma unroll
        for (int j = 0; j < 4; j++) acc[i][j] = 0.f;

    int ty = tid >> 4;   // row group for compute
    int tx = tid & 15;   // col group for compute

    for (int k0 = 0; k0 < INF_; k0 += 16) {
        float4 av;
        if (arow >= 0) {
            uint2 raw = *(const uint2*)(aptr + k0);
            float2 f0 = __half22float2(*(__half2*)&raw.x);
            float2 f1 = __half22float2(*(__half2*)&raw.y);
            av = make_float4(f0.x, f0.y, f1.x, f1.y);
        } else {
            av = make_float4(0.f, 0.f, 0.f, 0.f);
        }
        float4 bv = *(const float4*)(B + (size_t)(k0 + bk) * OUTF + bn);
        __syncthreads();
        As[ak + 0][am] = av.x; As[ak + 1][am] = av.y;
        As[ak + 2][am] = av.z; As[ak + 3][am] = av.w;
        *(float4*)&Bs[bk][bn] = bv;
        __syncthreads();
#pragma unroll
        for (int kk = 0; kk < 16; kk++) {
            float4 a4 = *(const float4*)&As[kk][ty * 4];
            float4 b4 = *(const float4*)&Bs[kk][tx * 4];
            acc[0][0] += a4.x * b4.x; acc[0][1] += a4.x * b4.y; acc[0][2] += a4.x * b4.z; acc[0][3] += a4.x * b4.w;
            acc[1][0] += a4.y * b4.x; acc[1][1] += a4.y * b4.y; acc[1][2] += a4.y * b4.z; acc[1][3] += a4.y * b4.w;
            acc[2][0] += a4.z * b4.x; acc[2][1] += a4.z * b4.y; acc[2][2] += a4.z * b4.z; acc[2][3] += a4.z * b4.w;
            acc[3][0] += a4.w * b4.x; acc[3][1] += a4.w * b4.y; acc[3][2] += a4.w * b4.z; acc[3][3] += a4.w * b4.w;
        }
    }

    int cbase = blockIdx.y * 64 + tx * 4;
#pragma unroll
    for (int i = 0; i < 4; i++) {
        int r = ridx[ty * 4 + i];
        if (r >= 0) {
#pragma unroll
            for (int j = 0; j < 4; j++)
                out[(size_t)r * OUTF + cbase + j] = acc[i][j] + bias[cbase + j];
        }
    }
}

// ---------------- launcher --------------------------------------------------
extern "C" void kernel_launch(void* const* d_in, const int* in_sizes, int n_in,
                              void* d_out, int out_size) {
    const float* x    = (const float*)d_in[0];
    const float* adj  = (const float*)d_in[1];
    const float* W1   = (const float*)d_in[2];
    const float* a1   = (const float*)d_in[3];
    const float* W2   = (const float*)d_in[4];
    const float* a2   = (const float*)d_in[5];
    const float* Wsgc = (const float*)d_in[6];
    const float* bsgc = (const float*)d_in[7];
    float* out = (float*)d_out;

    k_build<<<NN, 256>>>(adj);
    k_cvt<<<NN * INF_ / 1024, 256>>>(x);
    k_h<<<NN / 8, 256>>>(x, W1, a1);
    k_softmax1<<<1, 1024>>>();
    k_gat1<<<NN / 8, 256>>>(W2, a2);
    k_sm2mask<<<1, 1024>>>();
    k_spmm_h<<<NN, 128>>>(0);        // y1 = adj   @ x
    k_spmm_h<<<NN, 128>>>(1);        // y2 = adj^2 @ x
    k_spmm_h<<<NN, 128>>>(2);        // y3 = adj^3 @ x (mask-gated)
    k_gemm<<<dim3(64, 4, 2), 256>>>(Wsgc, bsgc, out);
}

// round 3
// speedup vs baseline: 1.7481x; 1.7481x over previous
#include <cuda_runtime.h>
#include <cuda_fp16.h>
#include <math.h>

#define NN    4096
#define INF_  512
#define HID   8
#define OUTF  256
#define MAXD  128

// ---------------- scratch (static device globals) ---------------------------
__device__ int    g_deg[NN];
__device__ int    g_nbr[NN * MAXD];
__device__ float  g_phu[NN * HID];    // exp(dst1[j]) * h[j]   (unnormalized)
__device__ float  g_e1[NN];           // exp(dst1[j])
__device__ float  g_qu[NN];           // exp(d2[j]) * h2v[j]   (unnormalized)
__device__ float  g_e2[NN];           // exp(d2[j])
__device__ float  g_S1, g_S2;         // softmax denominators
__device__ int    g_rows[2][NN];      // [0]=mask==1 (y1,Wa), [1]=mask==0 (y3,Wc)
__device__ int    g_cnt[2];
__device__ int    g_skip3[NN];        // 1 -> y3[row] never read
__device__ int    g_need2[NN];        // 1 -> y2[row] is read by some y3 computation
__device__ __half g_xh [NN * INF_];   // x in fp16
__device__ __half g_y1h[NN * INF_];   // adj   @ x
__device__ __half g_y2h[NN * INF_];   // adj^2 @ x
__device__ __half g_y3h[NN * INF_];   // adj^3 @ x

// ---------------- 1) build neighbor lists (deterministic order) -------------
__global__ void k_build(const float* __restrict__ adj) {
    int row = blockIdx.x;
    int t   = threadIdx.x;           // 256 threads
    const float4* ar = (const float4*)(adj + (size_t)row * NN);

    float4 v[4];
    int cnt = 0;
#pragma unroll
    for (int i = 0; i < 4; i++) {
        v[i] = ar[t + i * 256];
        cnt += (v[i].x != 0.f) + (v[i].y != 0.f) + (v[i].z != 0.f) + (v[i].w != 0.f);
    }

    __shared__ int sc[256];
    sc[t] = cnt;
    __syncthreads();
    for (int d = 1; d < 256; d <<= 1) {
        int val = (t >= d) ? sc[t - d] : 0;
        __syncthreads();
        if (t >= d) sc[t] += val;
        __syncthreads();
    }
    int pos   = sc[t] - cnt;   // exclusive prefix
    int total = sc[255];

    int* nb = g_nbr + (size_t)row * MAXD;
#pragma unroll
    for (int i = 0; i < 4; i++) {
        int base = (t + i * 256) * 4;
        if (v[i].x != 0.f) { if (pos < MAXD) nb[pos] = base + 0; pos++; }
        if (v[i].y != 0.f) { if (pos < MAXD) nb[pos] = base + 1; pos++; }
        if (v[i].z != 0.f) { if (pos < MAXD) nb[pos] = base + 2; pos++; }
        if (v[i].w != 0.f) { if (pos < MAXD) nb[pos] = base + 3; pos++; }
    }
    if (t == 0) {
        g_deg[row]   = total < MAXD ? total : MAXD;
        g_need2[row] = 0;                 // reset per launch
    }
    if (row == 0 && t < 2) g_cnt[t] = 0;  // reset per launch
}

// ---------------- 1b) x -> fp16 copy ---------------------------------------
__global__ void k_cvt(const float* __restrict__ x) {
    int i = blockIdx.x * 256 + threadIdx.x;         // 2048 blocks
    float4 v = ((const float4*)x)[i];
    __half2 lo = __floats2half2_rn(v.x, v.y);
    __half2 hi = __floats2half2_rn(v.z, v.w);
    uint2 packed;
    packed.x = *(unsigned*)&lo;
    packed.y = *(unsigned*)&hi;
    ((uint2*)g_xh)[i] = packed;
}

// ------- 2) h = x @ W1; dst1 = h@a1[8:]; write e1 = exp(dst1), phu = e1*h ---
__global__ void k_h(const float* __restrict__ x, const float* __restrict__ W1,
                    const float* __restrict__ a1) {
    int lane = threadIdx.x & 31;
    int row  = blockIdx.x * 8 + (threadIdx.x >> 5);
    const float* xr = x + (size_t)row * INF_;

    float acc[HID];
#pragma unroll
    for (int f = 0; f < HID; f++) acc[f] = 0.f;

    for (int k = lane; k < INF_; k += 32) {
        float xv = xr[k];
        float4 wA = *(const float4*)(W1 + k * HID);
        float4 wB = *(const float4*)(W1 + k * HID + 4);
        acc[0] += xv * wA.x; acc[1] += xv * wA.y; acc[2] += xv * wA.z; acc[3] += xv * wA.w;
        acc[4] += xv * wB.x; acc[5] += xv * wB.y; acc[6] += xv * wB.z; acc[7] += xv * wB.w;
    }
#pragma unroll
    for (int f = 0; f < HID; f++)
        for (int o = 16; o; o >>= 1) acc[f] += __shfl_xor_sync(0xffffffffu, acc[f], o);

    if (lane == 0) {
        float d = 0.f;
#pragma unroll
        for (int f = 0; f < HID; f++) d += acc[f] * a1[HID + f];
        float e1 = expf(d);
        g_e1[row] = e1;
#pragma unroll
        for (int f = 0; f < HID; f++) g_phu[row * HID + f] = e1 * acc[f];
    }
}

// ---------------- 3) tiny reduction: S = sum over 4096 values ----------------
__global__ void k_red(int which) {
    const float* v = which ? g_e2 : g_e1;
    __shared__ float sred[32];
    int t = threadIdx.x;   // 1024
    float s = (v[t] + v[t + 1024]) + (v[t + 2048] + v[t + 3072]);
    for (int o = 16; o; o >>= 1) s += __shfl_xor_sync(0xffffffffu, s, o);
    if ((t & 31) == 0) sred[t >> 5] = s;
    __syncthreads();
    if (t < 32) {
        float r = sred[t];
        for (int o = 16; o; o >>= 1) r += __shfl_xor_sync(0xffffffffu, r, o);
        if (t == 0) { if (which) g_S2 = r; else g_S1 = r; }
    }
}

// --- 4) h1 = elu((adj @ phu)/S1); h2 = h1@W2; e2 = exp(h2*a2[1]); qu=e2*h2 --
__global__ void k_gat1(const float* __restrict__ W2, const float* __restrict__ a2) {
    int lane = threadIdx.x & 31;
    int row  = blockIdx.x * 8 + (threadIdx.x >> 5);
    int deg  = g_deg[row];
    const int* nb = g_nbr + (size_t)row * MAXD;

    float acc[HID];
#pragma unroll
    for (int f = 0; f < HID; f++) acc[f] = 0.f;

    for (int t = lane; t < deg; t += 32) {
        int j = nb[t];
        float4 A = *(const float4*)(g_phu + j * HID);
        float4 B = *(const float4*)(g_phu + j * HID + 4);
        acc[0] += A.x; acc[1] += A.y; acc[2] += A.z; acc[3] += A.w;
        acc[4] += B.x; acc[5] += B.y; acc[6] += B.z; acc[7] += B.w;
    }
#pragma unroll
    for (int f = 0; f < HID; f++)
        for (int o = 16; o; o >>= 1) acc[f] += __shfl_xor_sync(0xffffffffu, acc[f], o);

    if (lane == 0) {
        float invS = 1.f / g_S1;
        float h2 = 0.f;
#pragma unroll
        for (int f = 0; f < HID; f++) {
            float v = acc[f] * invS;
            v = v > 0.f ? v : (expf(v) - 1.f);   // elu
            h2 += v * W2[f];
        }
        float e2 = expf(h2 * a2[1]);
        g_e2[row] = e2;
        g_qu[row] = e2 * h2;
    }
}

// ------ 5) mask: s2 = (adj @ qu)/S2; elu; threshold; row lists; gating ------
__global__ void k_mask() {
    int lane = threadIdx.x & 31;
    int row  = blockIdx.x * 8 + (threadIdx.x >> 5);
    int deg  = g_deg[row];
    const int* nb = g_nbr + (size_t)row * MAXD;

    float s = 0.f;
    for (int t = lane; t < deg; t += 32) s += g_qu[nb[t]];
    for (int o = 16; o; o >>= 1) s += __shfl_xor_sync(0xffffffffu, s, o);

    int which;
    if (lane == 0) {
        float s2 = s / g_S2;
        float sc = s2 > 0.f ? s2 : (expf(s2) - 1.f);   // elu
        which = (sc > 0.7f) ? 0 : 1;
        g_skip3[row] = (which == 0);
        int pos = atomicAdd(&g_cnt[which], 1);
        g_rows[which][pos] = row;
    }
    which = __shfl_sync(0xffffffffu, which, 0);
    if (which == 1) {   // y3[row] will be computed -> its neighbors' y2 needed
        for (int t = lane; t < deg; t += 32) g_need2[nb[t]] = 1;  // idempotent
    }
}

// ---------------- 6) SpMM fp16: dst[row] = sum_{j in N(row)} src[j] ---------
// mode 0: xh -> y1h ; mode 1: y1h -> y2h (need2) ; mode 2: y2h -> y3h (!skip3)
__global__ void k_spmm_h(int mode) {
    const __half* __restrict__ src =
        (mode == 0) ? g_xh : ((mode == 1) ? g_y1h : g_y2h);
    __half* dst = (mode == 0) ? g_y1h : ((mode == 1) ? g_y2h : g_y3h);

    int row = blockIdx.x;
    if (mode == 1 && !g_need2[row]) return;
    if (mode == 2 &&  g_skip3[row]) return;

    __shared__ int nbs[MAXD];
    int deg = g_deg[row];
    for (int i = threadIdx.x; i < deg; i += 128) nbs[i] = g_nbr[(size_t)row * MAXD + i];
    __syncthreads();

    int c = threadIdx.x << 2;   // 128 threads * 4 halves = 512 cols
    float4 acc = make_float4(0.f, 0.f, 0.f, 0.f);

    int k = 0;
    for (; k + 8 <= deg; k += 8) {
        uint2 r[8];
#pragma unroll
        for (int u = 0; u < 8; u++)
            r[u] = *(const uint2*)(src + (size_t)nbs[k + u] * INF_ + c);
#pragma unroll
        for (int u = 0; u < 8; u++) {
            float2 f0 = __half22float2(*(__half2*)&r[u].x);
            float2 f1 = __half22float2(*(__half2*)&r[u].y);
            acc.x += f0.x; acc.y += f0.y; acc.z += f1.x; acc.w += f1.y;
        }
    }
    for (; k < deg; k++) {
        uint2 rv = *(const uint2*)(src + (size_t)nbs[k] * INF_ + c);
        float2 f0 = __half22float2(*(__half2*)&rv.x);
        float2 f1 = __half22float2(*(__half2*)&rv.y);
        acc.x += f0.x; acc.y += f0.y; acc.z += f1.x; acc.w += f1.y;
    }

    __half2 lo = __floats2half2_rn(acc.x, acc.y);
    __half2 hi = __floats2half2_rn(acc.z, acc.w);
    uint2 packed;
    packed.x = *(unsigned*)&lo;
    packed.y = *(unsigned*)&hi;
    *(uint2*)(dst + (size_t)row * INF_ + c) = packed;
}

// ---------------- 7) routed GEMM (both halves in one launch, fp16 A) --------
// z==0: rows with mask==1, A=g_y1h, W = W_sgc[   0: 512]
// z==1: rows with mask==0, A=g_y3h, W = W_sgc[1024:1536]
__global__ void k_gemm(const float* __restrict__ Wsgc, const float* __restrict__ bias,
                       float* __restrict__ out) {
    __shared__ float As[16][64];
    __shared__ float Bs[16][64];
    __shared__ int   ridx[64];

    int which = blockIdx.z;
    int cnt   = g_cnt[which];
    int rbase = blockIdx.x * 64;
    if (rbase >= cnt) return;

    const __half* A = which ? g_y3h : g_y1h;
    const float*  B = Wsgc + (which ? (size_t)1024 * OUTF : 0) + blockIdx.y * 64;

    int tid = threadIdx.x;   // 256
    if (tid < 64) {
        int li = rbase + tid;
        ridx[tid] = (li < cnt) ? g_rows[which][li] : -1;
    }
    __syncthreads();

    int am = tid >> 2;            // 0..63 : row in tile (A load)
    int ak = (tid & 3) * 4;       // 0,4,8,12 : k sub-offset (A load)
    int bk = tid >> 4;            // 0..15 : k row (B load)
    int bn = (tid & 15) * 4;      // 0..60 : col (B load)

    int arow = ridx[am];
    const __half* aptr = (arow >= 0) ? (A + (size_t)arow * INF_ + ak) : A;

    float acc[4][4];
#pragma unroll
    for (int i = 0; i < 4; i++)
#pragma unroll
        for (int j = 0; j < 4; j++) acc[i][j] = 0.f;

    int ty = tid >> 4;   // row group for compute
    int tx = tid & 15;   // col group for compute

    for (int k0 = 0; k0 < INF_; k0 += 16) {
        float4 av;
        if (arow >= 0) {
            uint2 raw = *(const uint2*)(aptr + k0);
            float2 f0 = __half22float2(*(__half2*)&raw.x);
            float2 f1 = __half22float2(*(__half2*)&raw.y);
            av = make_float4(f0.x, f0.y, f1.x, f1.y);
        } else {
            av = make_float4(0.f, 0.f, 0.f, 0.f);
        }
        float4 bv = *(const float4*)(B + (size_t)(k0 + bk) * OUTF + bn);
        __syncthreads();
        As[ak + 0][am] = av.x; As[ak + 1][am] = av.y;
        As[ak + 2][am] = av.z; As[ak + 3][am] = av.w;
        *(float4*)&Bs[bk][bn] = bv;
        __syncthreads();
#pragma unroll
        for (int kk = 0; kk < 16; kk++) {
            float4 a4 = *(const float4*)&As[kk][ty * 4];
            float4 b4 = *(const float4*)&Bs[kk][tx * 4];
            acc[0][0] += a4.x * b4.x; acc[0][1] += a4.x * b4.y; acc[0][2] += a4.x * b4.z; acc[0][3] += a4.x * b4.w;
            acc[1][0] += a4.y * b4.x; acc[1][1] += a4.y * b4.y; acc[1][2] += a4.y * b4.z; acc[1][3] += a4.y * b4.w;
            acc[2][0] += a4.z * b4.x; acc[2][1] += a4.z * b4.y; acc[2][2] += a4.z * b4.z; acc[2][3] += a4.z * b4.w;
            acc[3][0] += a4.w * b4.x; acc[3][1] += a4.w * b4.y; acc[3][2] += a4.w * b4.z; acc[3][3] += a4.w * b4.w;
        }
    }

    int cbase = blockIdx.y * 64 + tx * 4;
#pragma unroll
    for (int i = 0; i < 4; i++) {
        int r = ridx[ty * 4 + i];
        if (r >= 0) {
#pragma unroll
            for (int j = 0; j < 4; j++)
                out[(size_t)r * OUTF + cbase + j] = acc[i][j] + bias[cbase + j];
        }
    }
}

// ---------------- launcher --------------------------------------------------
extern "C" void kernel_launch(void* const* d_in, const int* in_sizes, int n_in,
                              void* d_out, int out_size) {
    const float* x    = (const float*)d_in[0];
    const float* adj  = (const float*)d_in[1];
    const float* W1   = (const float*)d_in[2];
    const float* a1   = (const float*)d_in[3];
    const float* W2   = (const float*)d_in[4];
    const float* a2   = (const float*)d_in[5];
    const float* Wsgc = (const float*)d_in[6];
    const float* bsgc = (const float*)d_in[7];
    float* out = (float*)d_out;

    k_build<<<NN, 256>>>(adj);
    k_cvt<<<NN * INF_ / 1024, 256>>>(x);
    k_h<<<NN / 8, 256>>>(x, W1, a1);
    k_red<<<1, 1024>>>(0);           // S1
    k_gat1<<<NN / 8, 256>>>(W2, a2);
    k_red<<<1, 1024>>>(1);           // S2
    k_mask<<<NN / 8, 256>>>();
    k_spmm_h<<<NN, 128>>>(0);        // y1 = adj   @ x
    k_spmm_h<<<NN, 128>>>(1);        // y2 = adj^2 @ x   (need2-gated)
    k_spmm_h<<<NN, 128>>>(2);        // y3 = adj^3 @ x   (skip3-gated)
    k_gemm<<<dim3(64, 4, 2), 256>>>(Wsgc, bsgc, out);
}

// round 4
// speedup vs baseline: 2.6169x; 1.4970x over previous
#include <cuda_runtime.h>
#include <cuda_fp16.h>
#include <mma.h>
#include <math.h>

using namespace nvcuda;

#define NN    4096
#define INF_  512
#define HID   8
#define OUTF  256
#define MAXD  128

// ---------------- scratch (static device globals) ---------------------------
__device__ int    g_deg[NN];
__device__ int    g_nbr[NN * MAXD];
__device__ float  g_phu[NN * HID];    // exp(dst1[j]) * h[j]   (unnormalized)
__device__ float  g_e1[NN];           // exp(dst1[j])
__device__ float  g_qu[NN];           // exp(d2[j]) * h2v[j]   (unnormalized)
__device__ float  g_e2[NN];           // exp(d2[j])
__device__ int    g_rows[2][NN];      // [0]=mask==1 (y1,Wa), [1]=mask==0 (y3,Wc)
__device__ int    g_cnt[2];
__device__ int    g_skip3[NN];        // 1 -> y3[row] never read
__device__ int    g_need2[NN];        // 1 -> y2[row] read by some y3 computation
__device__ __half g_xh [NN * INF_];   // x in fp16
__device__ __half g_y1h[NN * INF_];   // adj   @ x
__device__ __half g_y2h[NN * INF_];   // adj^2 @ x
__device__ __half g_y3h[NN * INF_];   // adj^3 @ x
__device__ __half g_WhA[INF_ * OUTF]; // W_sgc[0:512]     in fp16
__device__ __half g_WhC[INF_ * OUTF]; // W_sgc[1024:1536] in fp16

// ---- fused prelude: build nbr lists | x->fp16 | h=x@W1 chain | W->fp16 -----
// blocks [0,4096): build ; [4096,6144): cvt ; [6144,6656): h ;
// [6656,6784): WA cvt ; [6784,6912): WC cvt
__global__ void k_prelude(const float* __restrict__ adj, const float* __restrict__ x,
                          const float* __restrict__ W1, const float* __restrict__ a1,
                          const float* __restrict__ Wsgc) {
    int b = blockIdx.x;
    int t = threadIdx.x;          // 256

    if (b < 4096) {
        // ---------- build neighbor list for row b ----------
        int row = b;
        const float4* ar = (const float4*)(adj + (size_t)row * NN);
        float4 v[4];
        int cnt = 0;
#pragma unroll
        for (int i = 0; i < 4; i++) {
            v[i] = ar[t + i * 256];
            cnt += (v[i].x != 0.f) + (v[i].y != 0.f) + (v[i].z != 0.f) + (v[i].w != 0.f);
        }
        __shared__ int sc[256];
        sc[t] = cnt;
        __syncthreads();
        for (int d = 1; d < 256; d <<= 1) {
            int val = (t >= d) ? sc[t - d] : 0;
            __syncthreads();
            if (t >= d) sc[t] += val;
            __syncthreads();
        }
        int pos   = sc[t] - cnt;
        int total = sc[255];
        int* nb = g_nbr + (size_t)row * MAXD;
#pragma unroll
        for (int i = 0; i < 4; i++) {
            int base = (t + i * 256) * 4;
            if (v[i].x != 0.f) { if (pos < MAXD) nb[pos] = base + 0; pos++; }
            if (v[i].y != 0.f) { if (pos < MAXD) nb[pos] = base + 1; pos++; }
            if (v[i].z != 0.f) { if (pos < MAXD) nb[pos] = base + 2; pos++; }
            if (v[i].w != 0.f) { if (pos < MAXD) nb[pos] = base + 3; pos++; }
        }
        if (t == 0) {
            g_deg[row]   = total < MAXD ? total : MAXD;
            g_need2[row] = 0;
        }
        if (row == 0 && t < 2) g_cnt[t] = 0;
    } else if (b < 6144) {
        // ---------- x -> fp16 ----------
        int i = (b - 4096) * 256 + t;          // 524288 float4 total
        float4 v = ((const float4*)x)[i];
        __half2 lo = __floats2half2_rn(v.x, v.y);
        __half2 hi = __floats2half2_rn(v.z, v.w);
        uint2 packed;
        packed.x = *(unsigned*)&lo;
        packed.y = *(unsigned*)&hi;
        ((uint2*)g_xh)[i] = packed;
    } else if (b < 6656) {
        // ---------- h = x @ W1 ; e1 = exp(h@a1[8:]); phu = e1*h ----------
        int lane = t & 31;
        int row  = (b - 6144) * 8 + (t >> 5);
        const float* xr = x + (size_t)row * INF_;
        float acc[HID];
#pragma unroll
        for (int f = 0; f < HID; f++) acc[f] = 0.f;
        for (int k = lane; k < INF_; k += 32) {
            float xv = xr[k];
            float4 wA = *(const float4*)(W1 + k * HID);
            float4 wB = *(const float4*)(W1 + k * HID + 4);
            acc[0] += xv * wA.x; acc[1] += xv * wA.y; acc[2] += xv * wA.z; acc[3] += xv * wA.w;
            acc[4] += xv * wB.x; acc[5] += xv * wB.y; acc[6] += xv * wB.z; acc[7] += xv * wB.w;
        }
#pragma unroll
        for (int f = 0; f < HID; f++)
            for (int o = 16; o; o >>= 1) acc[f] += __shfl_xor_sync(0xffffffffu, acc[f], o);
        if (lane == 0) {
            float d = 0.f;
#pragma unroll
            for (int f = 0; f < HID; f++) d += acc[f] * a1[HID + f];
            float e1 = expf(d);
            g_e1[row] = e1;
#pragma unroll
            for (int f = 0; f < HID; f++) g_phu[row * HID + f] = e1 * acc[f];
        }
    } else {
        // ---------- W_sgc blocks -> fp16 ----------
        int which = (b >= 6784);
        int base  = which ? 6784 : 6656;
        const float* src = Wsgc + (which ? (size_t)1024 * OUTF : 0);
        __half* dst = which ? g_WhC : g_WhA;
        int i = (b - base) * 256 + t;          // 32768 float4 per block-range
        float4 v = ((const float4*)src)[i];
        __half2 lo = __floats2half2_rn(v.x, v.y);
        __half2 hi = __floats2half2_rn(v.z, v.w);
        uint2 packed;
        packed.x = *(unsigned*)&lo;
        packed.y = *(unsigned*)&hi;
        ((uint2*)dst)[i] = packed;
    }
}

// ---- block-redundant sum of 4096 floats (deterministic order) --------------
__device__ __forceinline__ float block_sum4096(const float* v, int t) {
    __shared__ float sred[8];
    __shared__ float sbc;
    float s = 0.f;
    const float4* v4 = (const float4*)v;
#pragma unroll
    for (int i = 0; i < 4; i++) {
        float4 a = v4[t + i * 256];
        s += (a.x + a.y) + (a.z + a.w);
    }
    for (int o = 16; o; o >>= 1) s += __shfl_xor_sync(0xffffffffu, s, o);
    if ((t & 31) == 0) sred[t >> 5] = s;
    __syncthreads();
    if (t < 32) {
        float r = (t < 8) ? sred[t] : 0.f;
        for (int o = 4; o; o >>= 1) r += __shfl_xor_sync(0xffffffffu, r, o);
        if (t == 0) sbc = r;
    }
    __syncthreads();
    return sbc;
}

// --- gat1: h1 = elu((adj@phu)/S1); h2 = h1@W2; e2 = exp(h2*a2[1]); qu=e2*h2 -
__global__ void k_gat1(const float* __restrict__ W2, const float* __restrict__ a2) {
    int t    = threadIdx.x;
    float S1 = block_sum4096(g_e1, t);

    int lane = t & 31;
    int row  = blockIdx.x * 8 + (t >> 5);
    int deg  = g_deg[row];
    const int* nb = g_nbr + (size_t)row * MAXD;

    float acc[HID];
#pragma unroll
    for (int f = 0; f < HID; f++) acc[f] = 0.f;

    for (int k = lane; k < deg; k += 32) {
        int j = nb[k];
        float4 A = *(const float4*)(g_phu + j * HID);
        float4 B = *(const float4*)(g_phu + j * HID + 4);
        acc[0] += A.x; acc[1] += A.y; acc[2] += A.z; acc[3] += A.w;
        acc[4] += B.x; acc[5] += B.y; acc[6] += B.z; acc[7] += B.w;
    }
#pragma unroll
    for (int f = 0; f < HID; f++)
        for (int o = 16; o; o >>= 1) acc[f] += __shfl_xor_sync(0xffffffffu, acc[f], o);

    if (lane == 0) {
        float invS = 1.f / S1;
        float h2 = 0.f;
#pragma unroll
        for (int f = 0; f < HID; f++) {
            float v = acc[f] * invS;
            v = v > 0.f ? v : (expf(v) - 1.f);   // elu
            h2 += v * W2[f];
        }
        float e2 = expf(h2 * a2[1]);
        g_e2[row] = e2;
        g_qu[row] = e2 * h2;
    }
}

// ---- mask: s2 = (adj@qu)/S2; elu; threshold; row lists; SpMM gating --------
__global__ void k_mask() {
    int t    = threadIdx.x;
    float S2 = block_sum4096(g_e2, t);

    int lane = t & 31;
    int row  = blockIdx.x * 8 + (t >> 5);
    int deg  = g_deg[row];
    const int* nb = g_nbr + (size_t)row * MAXD;

    float s = 0.f;
    for (int k = lane; k < deg; k += 32) s += g_qu[nb[k]];
    for (int o = 16; o; o >>= 1) s += __shfl_xor_sync(0xffffffffu, s, o);

    int which;
    if (lane == 0) {
        float s2 = s / S2;
        float sc = s2 > 0.f ? s2 : (expf(s2) - 1.f);   // elu
        which = (sc > 0.7f) ? 0 : 1;
        g_skip3[row] = (which == 0);
        int pos = atomicAdd(&g_cnt[which], 1);
        g_rows[which][pos] = row;
    }
    which = __shfl_sync(0xffffffffu, which, 0);
    if (which == 1) {   // y3[row] computed -> its neighbors' y2 needed
        for (int k = lane; k < deg; k += 32) g_need2[nb[k]] = 1;  // idempotent
    }
}

// ---- SpMM fp16, 16B/thread: dst[row] = sum_{j in N(row)} src[j] ------------
// mode 0: xh -> y1h ; mode 1: y1h -> y2h (need2) ; mode 2: y2h -> y3h (!skip3)
__global__ void k_spmm_h(int mode) {
    const __half* __restrict__ src =
        (mode == 0) ? g_xh : ((mode == 1) ? g_y1h : g_y2h);
    __half* dst = (mode == 0) ? g_y1h : ((mode == 1) ? g_y2h : g_y3h);

    int row = blockIdx.x;
    if (mode == 1 && !g_need2[row]) return;
    if (mode == 2 &&  g_skip3[row]) return;

    __shared__ int nbs[MAXD];
    int deg = g_deg[row];
    for (int i = threadIdx.x; i < deg; i += 64) nbs[i] = g_nbr[(size_t)row * MAXD + i];
    __syncthreads();

    int c = threadIdx.x << 3;   // 64 threads * 8 halves = 512 cols
    float acc[8];
#pragma unroll
    for (int i = 0; i < 8; i++) acc[i] = 0.f;

    int k = 0;
    for (; k + 8 <= deg; k += 8) {
        uint4 r[8];
#pragma unroll
        for (int u = 0; u < 8; u++)
            r[u] = *(const uint4*)(src + (size_t)nbs[k + u] * INF_ + c);
#pragma unroll
        for (int u = 0; u < 8; u++) {
            float2 f0 = __half22float2(*(__half2*)&r[u].x);
            float2 f1 = __half22float2(*(__half2*)&r[u].y);
            float2 f2 = __half22float2(*(__half2*)&r[u].z);
            float2 f3 = __half22float2(*(__half2*)&r[u].w);
            acc[0] += f0.x; acc[1] += f0.y; acc[2] += f1.x; acc[3] += f1.y;
            acc[4] += f2.x; acc[5] += f2.y; acc[6] += f3.x; acc[7] += f3.y;
        }
    }
    for (; k < deg; k++) {
        uint4 rv = *(const uint4*)(src + (size_t)nbs[k] * INF_ + c);
        float2 f0 = __half22float2(*(__half2*)&rv.x);
        float2 f1 = __half22float2(*(__half2*)&rv.y);
        float2 f2 = __half22float2(*(__half2*)&rv.z);
        float2 f3 = __half22float2(*(__half2*)&rv.w);
        acc[0] += f0.x; acc[1] += f0.y; acc[2] += f1.x; acc[3] += f1.y;
        acc[4] += f2.x; acc[5] += f2.y; acc[6] += f3.x; acc[7] += f3.y;
    }

    uint4 packed;
    __half2 h0 = __floats2half2_rn(acc[0], acc[1]);
    __half2 h1 = __floats2half2_rn(acc[2], acc[3]);
    __half2 h2 = __floats2half2_rn(acc[4], acc[5]);
    __half2 h3 = __floats2half2_rn(acc[6], acc[7]);
    packed.x = *(unsigned*)&h0; packed.y = *(unsigned*)&h1;
    packed.z = *(unsigned*)&h2; packed.w = *(unsigned*)&h3;
    *(uint4*)(dst + (size_t)row * INF_ + c) = packed;
}

// ---- routed GEMM via wmma (HMMA fp16 -> fp32 acc) --------------------------
// grid (64, 2, 2): 64 row-tiles x 2 col-halves x which. Block 256 = 8 warps.
// Tile: 64 rows x 128 cols, K=512 in chunks of 64.
#define LDA_S 72     // halves (64 + 8 pad)
#define LDB_S 136    // halves (128 + 8 pad)
#define LDS_F 132    // floats (128 + 4 pad)

__global__ void k_gemm(const float* __restrict__ bias, float* __restrict__ out) {
    __shared__ __align__(16) char buf[64 * LDS_F * 4];   // 33792 B, aliased
    __shared__ int ridx[64];

    __half* sA = (__half*)buf;                 // [64][LDA_S] = 9216 B
    __half* sB = (__half*)(buf + 64 * LDA_S * 2); // [64][LDB_S] = 17408 B
    float*  stage = (float*)buf;               // [64][LDS_F] after MMA

    int which = blockIdx.z;
    int cnt   = g_cnt[which];
    int rbase = blockIdx.x * 64;
    if (rbase >= cnt) return;

    const __half* A = which ? g_y3h : g_y1h;
    const __half* W = which ? g_WhC : g_WhA;
    int cb = blockIdx.y * 128;

    int t = threadIdx.x;   // 256
    int warp = t >> 5;
    int wrow = warp & 3;          // 0..3 -> 16-row strip
    int wcol = warp >> 2;         // 0..1 -> 64-col half

    if (t < 64) {
        int li = rbase + t;
        ridx[t] = (li < cnt) ? g_rows[which][li] : -1;
    }
    __syncthreads();

    // A gather source row (clamped; invalid rows never stored)
    int myArow0 = ridx[t >> 2];
    const __half* aSrc = A + (size_t)(myArow0 < 0 ? 0 : myArow0) * INF_;
    int apart = t & 3;

    wmma::fragment<wmma::accumulator, 16, 16, 16, float> cfr[4];
#pragma unroll
    for (int j = 0; j < 4; j++) wmma::fill_fragment(cfr[j], 0.f);

    for (int kc = 0; kc < INF_; kc += 64) {
        // load A chunk: 64 rows x 64 halves
#pragma unroll
        for (int u = 0; u < 2; u++) {
            int chunk = apart * 2 + u;                 // 0..7 (8 halves each)
            uint4 v = *(const uint4*)(aSrc + kc + chunk * 8);
            *(uint4*)(sA + (t >> 2) * LDA_S + chunk * 8) = v;
        }
        // load B chunk: 64 k-rows x 128 halves
#pragma unroll
        for (int v4 = 0; v4 < 4; v4++) {
            int idx = v4 * 256 + t;                    // 0..1023
            int krow = idx >> 4, chunk = idx & 15;
            uint4 v = *(const uint4*)(W + (size_t)(kc + krow) * OUTF + cb + chunk * 8);
            *(uint4*)(sB + krow * LDB_S + chunk * 8) = v;
        }
        __syncthreads();

#pragma unroll
        for (int ks = 0; ks < 4; ks++) {
            wmma::fragment<wmma::matrix_a, 16, 16, 16, __half, wmma::row_major> afr;
            wmma::load_matrix_sync(afr, sA + wrow * 16 * LDA_S + ks * 16, LDA_S);
#pragma unroll
            for (int j = 0; j < 4; j++) {
                wmma::fragment<wmma::matrix_b, 16, 16, 16, __half, wmma::row_major> bfr;
                wmma::load_matrix_sync(bfr, sB + ks * 16 * LDB_S + wcol * 64 + j * 16, LDB_S);
                wmma::mma_sync(cfr[j], afr, bfr, cfr[j]);
            }
        }
        __syncthreads();
    }

    // stage accumulators to smem (overlaps sA/sB, safe after sync)
#pragma unroll
    for (int j = 0; j < 4; j++)
        wmma::store_matrix_sync(stage + wrow * 16 * LDS_F + wcol * 64 + j * 16,
                                cfr[j], LDS_F, wmma::mem_row_major);
    __syncthreads();

    // scatter to out with bias
#pragma unroll
    for (int w = 0; w < 8; w++) {
        int idx = w * 256 + t;              // 0..2047
        int rl = idx >> 5, chunk = idx & 31;
        int col = chunk * 4;
        int grow = ridx[rl];
        if (grow >= 0) {
            float4 v = *(const float4*)(stage + rl * LDS_F + col);
            float4 bv = *(const float4*)(bias + cb + col);
            v.x += bv.x; v.y += bv.y; v.z += bv.z; v.w += bv.w;
            *(float4*)(out + (size_t)grow * OUTF + cb + col) = v;
        }
    }
}

// ---------------- launcher --------------------------------------------------
extern "C" void kernel_launch(void* const* d_in, const int* in_sizes, int n_in,
                              void* d_out, int out_size) {
    const float* x    = (const float*)d_in[0];
    const float* adj  = (const float*)d_in[1];
    const float* W1   = (const float*)d_in[2];
    const float* a1   = (const float*)d_in[3];
    const float* W2   = (const float*)d_in[4];
    const float* a2   = (const float*)d_in[5];
    const float* Wsgc = (const float*)d_in[6];
    const float* bsgc = (const float*)d_in[7];
    float* out = (float*)d_out;

    k_prelude<<<6912, 256>>>(adj, x, W1, a1, Wsgc);
    k_gat1<<<NN / 8, 256>>>(W2, a2);
    k_mask<<<NN / 8, 256>>>();
    k_spmm_h<<<NN, 64>>>(0);         // y1 = adj   @ x
    k_spmm_h<<<NN, 64>>>(1);         // y2 = adj^2 @ x   (need2-gated)
    k_spmm_h<<<NN, 64>>>(2);         // y3 = adj^3 @ x   (skip3-gated)
    k_gemm<<<dim3(64, 2, 2), 256>>>(bsgc, out);
}